// round 1
// baseline (speedup 1.0000x reference)
#include <cuda_runtime.h>
#include <cstdint>
#include <math.h>

#define N_LEVELS 16
#define LOG2_HASHMAP 19
#define TABLE_ROWS (1u << LOG2_HASHMAP)
#define TPB 256
#define SROW 37   // 35 outputs + pad; stride 37 is odd -> conflict-free column writes

struct LevelParams {
    float res[N_LEVELS];
    unsigned int hs[N_LEVELS];
    unsigned long long magic[N_LEVELS];
};

__global__ __launch_bounds__(TPB) void hashgrid_kernel(
    const float* __restrict__ x,
    const float* __restrict__ tables,
    float* __restrict__ out,
    int n, LevelParams P)
{
    __shared__ float s[TPB * SROW];
    int i = blockIdx.x * TPB + threadIdx.x;

    float px = 0.f, py = 0.f, pz = 0.f;
    if (i < n) {
        size_t bi = 3ull * (size_t)i;
        px = x[bi]; py = x[bi + 1]; pz = x[bi + 2];
    }
    float* row = s + threadIdx.x * SROW;
    row[0] = px; row[1] = py; row[2] = pz;

    const unsigned P1 = 2654435761u, P2 = 805459861u;

    #pragma unroll
    for (int l = 0; l < N_LEVELS; ++l) {
        float r = P.res[l];
        float xs0 = px * r, xs1 = py * r, xs2 = pz * r;
        int i0 = (int)xs0, i1 = (int)xs1, i2 = (int)xs2;   // trunc == astype(int32), x>=0
        float f0 = xs0 - (float)i0;
        float f1 = xs1 - (float)i1;
        float f2 = xs2 - (float)i2;

        float wx[2] = {1.f - f0, f0};
        float wy[2] = {1.f - f1, f1};
        float wz[2] = {1.f - f2, f2};

        unsigned a[2] = {(unsigned)i0,      (unsigned)i0 + 1u};
        unsigned b[2] = {(unsigned)i1 * P1, (unsigned)i1 * P1 + P1};
        unsigned c[2] = {(unsigned)i2 * P2, (unsigned)i2 * P2 + P2};

        const float2* tbl = (const float2*)tables + (size_t)l * TABLE_ROWS;
        unsigned hs = P.hs[l];
        unsigned long long M = P.magic[l];

        float acc0 = 0.f, acc1 = 0.f;
        #pragma unroll
        for (int cz = 0; cz < 2; ++cz)
        #pragma unroll
        for (int cy = 0; cy < 2; ++cy)
        #pragma unroll
        for (int cx = 0; cx < 2; ++cx) {
            unsigned h = a[cx] ^ b[cy] ^ c[cz];
            // exact h % hs via magic multiply: M = ceil(2^64/hs), error < 2^-32 < 1/hs
            unsigned q = (unsigned)__umul64hi((unsigned long long)h, M);
            unsigned hid = h - q * hs;
            float2 t = __ldg(tbl + hid);
            float w = wx[cx] * wy[cy] * wz[cz];
            acc0 = fmaf(t.x, w, acc0);
            acc1 = fmaf(t.y, w, acc1);
        }
        row[3 + 2 * l]     = acc0;
        row[3 + 2 * l + 1] = acc1;
    }

    __syncthreads();

    // coalesced write-out: this block owns out[base .. base + TPB*35)
    size_t base  = (size_t)blockIdx.x * (TPB * 35);
    size_t total = (size_t)n * 35ull;
    #pragma unroll
    for (int e = threadIdx.x; e < TPB * 35; e += TPB) {
        size_t g = base + (size_t)e;
        if (g < total) {
            int p = e / 35, cc = e % 35;
            out[g] = s[p * SROW + cc];
        }
    }
}

extern "C" void kernel_launch(void* const* d_in, const int* in_sizes, int n_in,
                              void* d_out, int out_size)
{
    const float* x      = (const float*)d_in[0];
    const float* tables = (const float*)d_in[1];
    float* out          = (float*)d_out;
    int n = in_sizes[0] / 3;

    // Level params: identical double-precision formula as the reference.
    LevelParams P;
    double beta = exp((log(2048.0) - log(16.0)) / 15.0);
    for (int l = 0; l < N_LEVELS; ++l) {
        double rr = floor(16.0 * pow(beta, (double)l));
        P.res[l] = (float)rr;
        unsigned long long r3 = (unsigned long long)rr;
        r3 = r3 * r3 * r3;
        unsigned long long cap = 1ull << LOG2_HASHMAP;
        unsigned hs = (unsigned)((r3 < cap) ? r3 : cap);
        P.hs[l]    = hs;
        P.magic[l] = (~0ull) / (unsigned long long)hs + 1ull;  // exact for pow2 too
    }

    int blocks = (n + TPB - 1) / TPB;
    hashgrid_kernel<<<blocks, TPB>>>(x, tables, out, n, P);
}

// round 2
// speedup vs baseline: 2.5044x; 2.5044x over previous
#include <cuda_runtime.h>
#include <cstdint>
#include <math.h>

#define N_LEVELS 16
#define LOG2_HASHMAP 19
#define TABLE_ROWS (1u << LOG2_HASHMAP)
#define TPB 256
#define PPB 64              // points per block; 4 threads per point, 4 levels each
#define LPT 4               // levels per thread

struct LevelParams {
    float res[N_LEVELS];
    unsigned int hs[N_LEVELS];
    unsigned long long magic[N_LEVELS];
};

__global__ __launch_bounds__(TPB) void hashgrid_kernel(
    const float* __restrict__ x,
    const float* __restrict__ tables,
    float* __restrict__ out,
    int n, LevelParams P)
{
    __shared__ float s[PPB * 35];
    int tid = threadIdx.x;
    int p   = tid & (PPB - 1);   // point within block
    int h   = tid >> 6;          // which quarter of levels: 0..3
    int i   = blockIdx.x * PPB + p;

    float px = 0.f, py = 0.f, pz = 0.f;
    if (i < n) {
        size_t bi = 3ull * (size_t)i;
        px = x[bi]; py = x[bi + 1]; pz = x[bi + 2];
    }
    float* row = s + p * 35;
    if (h == 0) { row[0] = px; row[1] = py; row[2] = pz; }

    const unsigned PR1 = 2654435761u, PR2 = 805459861u;

    #pragma unroll
    for (int k = 0; k < LPT; ++k) {
        int l = h + 4 * k;               // thread h handles levels h, h+4, h+8, h+12
        float r = P.res[l];
        float xs0 = px * r, xs1 = py * r, xs2 = pz * r;
        int i0 = (int)xs0, i1 = (int)xs1, i2 = (int)xs2;   // trunc == astype(int32), x>=0
        float f0 = xs0 - (float)i0;
        float f1 = xs1 - (float)i1;
        float f2 = xs2 - (float)i2;

        float wx[2] = {1.f - f0, f0};
        float wy[2] = {1.f - f1, f1};
        float wz[2] = {1.f - f2, f2};

        unsigned a[2] = {(unsigned)i0,       (unsigned)i0 + 1u};
        unsigned b[2] = {(unsigned)i1 * PR1, (unsigned)i1 * PR1 + PR1};
        unsigned c[2] = {(unsigned)i2 * PR2, (unsigned)i2 * PR2 + PR2};

        const float2* tbl = (const float2*)tables + (size_t)l * TABLE_ROWS;
        unsigned hs = P.hs[l];
        unsigned long long M = P.magic[l];

        // compute all 8 hash indices first, then issue all 8 gathers back-to-back
        unsigned hid[8];
        #pragma unroll
        for (int cz = 0; cz < 2; ++cz)
        #pragma unroll
        for (int cy = 0; cy < 2; ++cy)
        #pragma unroll
        for (int cx = 0; cx < 2; ++cx) {
            unsigned hh = a[cx] ^ b[cy] ^ c[cz];
            unsigned q = (unsigned)__umul64hi((unsigned long long)hh, M);
            hid[cz * 4 + cy * 2 + cx] = hh - q * hs;
        }
        float2 t[8];
        #pragma unroll
        for (int e = 0; e < 8; ++e) t[e] = __ldg(tbl + hid[e]);

        float acc0 = 0.f, acc1 = 0.f;
        #pragma unroll
        for (int cz = 0; cz < 2; ++cz)
        #pragma unroll
        for (int cy = 0; cy < 2; ++cy)
        #pragma unroll
        for (int cx = 0; cx < 2; ++cx) {
            int e = cz * 4 + cy * 2 + cx;
            float w = wx[cx] * wy[cy] * wz[cz];
            acc0 = fmaf(t[e].x, w, acc0);
            acc1 = fmaf(t[e].y, w, acc1);
        }
        row[3 + 2 * l]     = acc0;
        row[3 + 2 * l + 1] = acc1;
    }

    __syncthreads();

    // coalesced write-out: this block owns out[base .. base + PPB*35)
    size_t base  = (size_t)blockIdx.x * (PPB * 35);
    size_t total = (size_t)n * 35ull;
    #pragma unroll
    for (int e = tid; e < PPB * 35; e += TPB) {
        size_t g = base + (size_t)e;
        if (g < total) out[g] = s[e];
    }
}

extern "C" void kernel_launch(void* const* d_in, const int* in_sizes, int n_in,
                              void* d_out, int out_size)
{
    const float* x      = (const float*)d_in[0];
    const float* tables = (const float*)d_in[1];
    float* out          = (float*)d_out;
    int n = in_sizes[0] / 3;

    // Level params: identical double-precision formula as the reference.
    LevelParams P;
    double beta = exp((log(2048.0) - log(16.0)) / 15.0);
    for (int l = 0; l < N_LEVELS; ++l) {
        double rr = floor(16.0 * pow(beta, (double)l));
        P.res[l] = (float)rr;
        unsigned long long r3 = (unsigned long long)rr;
        r3 = r3 * r3 * r3;
        unsigned long long cap = 1ull << LOG2_HASHMAP;
        unsigned hs = (unsigned)((r3 < cap) ? r3 : cap);
        P.hs[l]    = hs;
        P.magic[l] = (~0ull) / (unsigned long long)hs + 1ull;  // exact for pow2 too
    }

    int blocks = (n + PPB - 1) / PPB;
    hashgrid_kernel<<<blocks, TPB>>>(x, tables, out, n, P);
}

// round 3
// speedup vs baseline: 2.5861x; 1.0326x over previous
#include <cuda_runtime.h>
#include <cstdint>
#include <math.h>

#define N_LEVELS 16
#define LOG2_HASHMAP 19
#define TABLE_ROWS (1u << LOG2_HASHMAP)
#define TPB 256
#define PPB 64              // points per block; 4 threads per point, 4 levels each
#define LPT 4               // levels per thread

struct LevelParams {
    float res[N_LEVELS];
    unsigned int hs[N_LEVELS];
    unsigned long long magic[N_LEVELS];
};

__device__ __forceinline__ unsigned mod_hs(unsigned h, unsigned hs, unsigned long long M) {
    unsigned q = (unsigned)__umul64hi((unsigned long long)h, M);
    return h - q * hs;
}

__global__ __launch_bounds__(TPB) void hashgrid_kernel(
    const float* __restrict__ x,
    const float* __restrict__ tables,
    float* __restrict__ out,
    int n, LevelParams P)
{
    __shared__ float s[PPB * 35];
    int tid = threadIdx.x;
    int p   = tid & (PPB - 1);   // point within block
    int h   = tid >> 6;          // which quarter of levels: 0..3
    int i   = blockIdx.x * PPB + p;

    float px = 0.f, py = 0.f, pz = 0.f;
    if (i < n) {
        size_t bi = 3ull * (size_t)i;
        px = x[bi]; py = x[bi + 1]; pz = x[bi + 2];
    }
    float* row = s + p * 35;
    if (h == 0) { row[0] = px; row[1] = py; row[2] = pz; }

    const unsigned PR1 = 2654435761u, PR2 = 805459861u;

    #pragma unroll
    for (int k = 0; k < LPT; ++k) {
        int l = h + 4 * k;               // thread h handles levels h, h+4, h+8, h+12
        float r = P.res[l];
        float xs0 = px * r, xs1 = py * r, xs2 = pz * r;
        int i0 = (int)xs0, i1 = (int)xs1, i2 = (int)xs2;   // trunc == astype(int32), x>=0
        float f0 = xs0 - (float)i0;
        float f1 = xs1 - (float)i1;
        float f2 = xs2 - (float)i2;

        float wx0 = 1.f - f0;
        float wy[2] = {1.f - f1, f1};
        float wz[2] = {1.f - f2, f2};

        unsigned a0 = (unsigned)i0;
        unsigned a1 = a0 + 1u;
        unsigned b[2] = {(unsigned)i1 * PR1, (unsigned)i1 * PR1 + PR1};
        unsigned c[2] = {(unsigned)i2 * PR2, (unsigned)i2 * PR2 + PR2};

        const float2* tbl  = (const float2*)tables + (size_t)l * TABLE_ROWS;
        const float4* tbl4 = (const float4*)tbl;
        unsigned hs = P.hs[l];
        unsigned long long M = P.magic[l];

        bool odd = (i0 & 1) != 0;        // x-corner pair NOT contiguous when i0 odd

        // Per (cy,cz) pair: one float4 covering the aligned row-pair that contains
        // corner cx=0; corner cx=1 is the other half of that float4 when i0 is even
        // (h1 = h0^1 and hs is even for every level), else a separate gather.
        unsigned hid0[4];
        float4 v[4];
        float2 e1[4];
        #pragma unroll
        for (int q = 0; q < 4; ++q) {
            int cy = q & 1, cz = q >> 1;
            unsigned bc = b[cy] ^ c[cz];
            hid0[q] = mod_hs(a0 ^ bc, hs, M);
            v[q] = __ldg(tbl4 + (hid0[q] >> 1));
        }
        if (odd) {
            #pragma unroll
            for (int q = 0; q < 4; ++q) {
                int cy = q & 1, cz = q >> 1;
                unsigned bc = b[cy] ^ c[cz];
                e1[q] = __ldg(tbl + mod_hs(a1 ^ bc, hs, M));
            }
        }

        float acc0 = 0.f, acc1 = 0.f;
        #pragma unroll
        for (int q = 0; q < 4; ++q) {
            int cy = q & 1, cz = q >> 1;
            bool lo = (hid0[q] & 1u) == 0u;
            float2 t0 = lo ? make_float2(v[q].x, v[q].y) : make_float2(v[q].z, v[q].w);
            float2 t1;
            if (odd) t1 = e1[q];
            else     t1 = lo ? make_float2(v[q].z, v[q].w) : make_float2(v[q].x, v[q].y);
            float wyz = wy[cy] * wz[cz];
            float w0 = wx0 * wyz;
            float w1 = f0  * wyz;
            acc0 = fmaf(t0.x, w0, fmaf(t1.x, w1, acc0));
            acc1 = fmaf(t0.y, w0, fmaf(t1.y, w1, acc1));
        }
        row[3 + 2 * l]     = acc0;
        row[3 + 2 * l + 1] = acc1;
    }

    __syncthreads();

    // coalesced write-out: this block owns out[base .. base + PPB*35)
    size_t base  = (size_t)blockIdx.x * (PPB * 35);
    size_t total = (size_t)n * 35ull;
    #pragma unroll
    for (int e = tid; e < PPB * 35; e += TPB) {
        size_t g = base + (size_t)e;
        if (g < total) out[g] = s[e];
    }
}

extern "C" void kernel_launch(void* const* d_in, const int* in_sizes, int n_in,
                              void* d_out, int out_size)
{
    const float* x      = (const float*)d_in[0];
    const float* tables = (const float*)d_in[1];
    float* out          = (float*)d_out;
    int n = in_sizes[0] / 3;

    // Level params: identical double-precision formula as the reference.
    LevelParams P;
    double beta = exp((log(2048.0) - log(16.0)) / 15.0);
    for (int l = 0; l < N_LEVELS; ++l) {
        double rr = floor(16.0 * pow(beta, (double)l));
        P.res[l] = (float)rr;
        unsigned long long r3 = (unsigned long long)rr;
        r3 = r3 * r3 * r3;
        unsigned long long cap = 1ull << LOG2_HASHMAP;
        unsigned hs = (unsigned)((r3 < cap) ? r3 : cap);
        P.hs[l]    = hs;
        P.magic[l] = (~0ull) / (unsigned long long)hs + 1ull;  // exact for pow2 too
    }

    int blocks = (n + PPB - 1) / PPB;
    hashgrid_kernel<<<blocks, TPB>>>(x, tables, out, n, P);
}

// round 4
// speedup vs baseline: 2.7447x; 1.0614x over previous
#include <cuda_runtime.h>
#include <cstdint>
#include <math.h>

#define N_LEVELS 16
#define LOG2_HASHMAP 19
#define TABLE_ROWS (1u << LOG2_HASHMAP)
#define TPB 256
#define PPB 64              // points per block; 4 threads per point, 4 levels each
#define LPT 4               // levels per thread

struct LevelParams {
    float res[N_LEVELS];
    unsigned int hs[N_LEVELS];
    unsigned long long magic[N_LEVELS];
};

__device__ __forceinline__ unsigned mod_hs(unsigned h, unsigned hs, unsigned long long M) {
    unsigned q = (unsigned)__umul64hi((unsigned long long)h, M);
    return h - q * hs;
}

__global__ __launch_bounds__(TPB, 6) void hashgrid_kernel(
    const float* __restrict__ x,
    const float* __restrict__ tables,
    float* __restrict__ out,
    int n, LevelParams P)
{
    __shared__ float s[PPB * 35];
    int tid = threadIdx.x;
    int p   = tid & (PPB - 1);   // point within block
    int h   = tid >> 6;          // which quarter of levels: 0..3
    int i   = blockIdx.x * PPB + p;

    float px = 0.f, py = 0.f, pz = 0.f;
    if (i < n) {
        size_t bi = 3ull * (size_t)i;
        px = x[bi]; py = x[bi + 1]; pz = x[bi + 2];
    }
    float* row = s + p * 35;
    if (h == 0) { row[0] = px; row[1] = py; row[2] = pz; }

    const unsigned PR1 = 2654435761u, PR2 = 805459861u;

    #pragma unroll
    for (int k = 0; k < LPT; ++k) {
        int l = h + 4 * k;               // thread h handles levels h, h+4, h+8, h+12
        float r = P.res[l];
        float xs0 = px * r, xs1 = py * r, xs2 = pz * r;
        int i0 = (int)xs0, i1 = (int)xs1, i2 = (int)xs2;   // trunc == astype(int32), x>=0
        float f0 = xs0 - (float)i0;
        float f1 = xs1 - (float)i1;
        float f2 = xs2 - (float)i2;

        float wx0 = 1.f - f0;
        // wyz[q] for q = cz*2+cy
        float wyz[4];
        wyz[0] = (1.f - f1) * (1.f - f2);
        wyz[1] = f1 * (1.f - f2);
        wyz[2] = (1.f - f1) * f2;
        wyz[3] = f1 * f2;

        unsigned a0 = (unsigned)i0;
        unsigned a1 = a0 + 1u;
        unsigned b0 = (unsigned)i1 * PR1;
        unsigned c0 = (unsigned)i2 * PR2;
        unsigned bc[4];
        bc[0] = b0 ^ c0;
        bc[1] = (b0 + PR1) ^ c0;
        bc[2] = b0 ^ (c0 + PR2);
        bc[3] = (b0 + PR1) ^ (c0 + PR2);

        const float2* tbl  = (const float2*)tables + (size_t)l * TABLE_ROWS;
        const float4* tbl4 = (const float4*)tbl;
        unsigned hs = P.hs[l];
        unsigned long long M = P.magic[l];

        bool odd = (i0 & 1) != 0;        // x-corner pair NOT contiguous when i0 odd

        float acc0 = 0.f, acc1 = 0.f;

        // two groups of two (cy,cz) pairs: keeps live float4 state small
        #pragma unroll
        for (int g = 0; g < 2; ++g) {
            int qa = 2 * g, qb = 2 * g + 1;
            unsigned ha = mod_hs(a0 ^ bc[qa], hs, M);
            unsigned hb = mod_hs(a0 ^ bc[qb], hs, M);
            float4 va = __ldg(tbl4 + (ha >> 1));
            float4 vb = __ldg(tbl4 + (hb >> 1));
            float2 ea, eb;
            if (odd) {
                ea = __ldg(tbl + mod_hs(a1 ^ bc[qa], hs, M));
                eb = __ldg(tbl + mod_hs(a1 ^ bc[qb], hs, M));
            }
            // pair a
            {
                bool lo = (ha & 1u) == 0u;
                float t0x = lo ? va.x : va.z, t0y = lo ? va.y : va.w;
                float t1x, t1y;
                if (odd) { t1x = ea.x; t1y = ea.y; }
                else     { t1x = lo ? va.z : va.x; t1y = lo ? va.w : va.y; }
                float w0 = wx0 * wyz[qa];
                float w1 = f0  * wyz[qa];
                acc0 = fmaf(t0x, w0, fmaf(t1x, w1, acc0));
                acc1 = fmaf(t0y, w0, fmaf(t1y, w1, acc1));
            }
            // pair b
            {
                bool lo = (hb & 1u) == 0u;
                float t0x = lo ? vb.x : vb.z, t0y = lo ? vb.y : vb.w;
                float t1x, t1y;
                if (odd) { t1x = eb.x; t1y = eb.y; }
                else     { t1x = lo ? vb.z : vb.x; t1y = lo ? vb.w : vb.y; }
                float w0 = wx0 * wyz[qb];
                float w1 = f0  * wyz[qb];
                acc0 = fmaf(t0x, w0, fmaf(t1x, w1, acc0));
                acc1 = fmaf(t0y, w0, fmaf(t1y, w1, acc1));
            }
        }
        row[3 + 2 * l]     = acc0;
        row[3 + 2 * l + 1] = acc1;
    }

    __syncthreads();

    // coalesced vectorized write-out: block owns out[base .. base + PPB*35)
    // PPB*35 = 2240 floats = 560 float4; block byte base = blockIdx*8960 (16B aligned)
    size_t base = (size_t)blockIdx.x * (PPB * 35);
    if ((blockIdx.x + 1) * (size_t)(PPB * 35) <= (size_t)n * 35ull) {
        float4* o4 = (float4*)(out + base);
        const float4* s4 = (const float4*)s;
        #pragma unroll
        for (int e = tid; e < PPB * 35 / 4; e += TPB)
            o4[e] = s4[e];
    } else {
        size_t total = (size_t)n * 35ull;
        for (int e = tid; e < PPB * 35; e += TPB) {
            size_t g = base + (size_t)e;
            if (g < total) out[g] = s[e];
        }
    }
}

extern "C" void kernel_launch(void* const* d_in, const int* in_sizes, int n_in,
                              void* d_out, int out_size)
{
    const float* x      = (const float*)d_in[0];
    const float* tables = (const float*)d_in[1];
    float* out          = (float*)d_out;
    int n = in_sizes[0] / 3;

    // Level params: identical double-precision formula as the reference.
    LevelParams P;
    double beta = exp((log(2048.0) - log(16.0)) / 15.0);
    for (int l = 0; l < N_LEVELS; ++l) {
        double rr = floor(16.0 * pow(beta, (double)l));
        P.res[l] = (float)rr;
        unsigned long long r3 = (unsigned long long)rr;
        r3 = r3 * r3 * r3;
        unsigned long long cap = 1ull << LOG2_HASHMAP;
        unsigned hs = (unsigned)((r3 < cap) ? r3 : cap);
        P.hs[l]    = hs;
        P.magic[l] = (~0ull) / (unsigned long long)hs + 1ull;  // exact for pow2 too
    }

    int blocks = (n + PPB - 1) / PPB;
    hashgrid_kernel<<<blocks, TPB>>>(x, tables, out, n, P);
}